// round 2
// baseline (speedup 1.0000x reference)
#include <cuda_runtime.h>
#include <cuda_bf16.h>
#include <math.h>

#define Nn 16
#define Cc 64
#define Tt 300
#define Vv 25
#define NHh 4
#define Bb (Nn*Vv)          // 400
#define QKVO 192            // 2*DK+DV

// Scratch (static device memory; no runtime allocation)
__device__ float g_qkv[(size_t)Bb * QKVO * Tt];    // 23,040,000 floats
__device__ float g_attn[(size_t)Bb * 64 * Tt];     //  7,680,000 floats

// ---------------------------------------------------------------------------
// Kernel 1: fused data_bn (eval) + 1x1 qkv conv. 2 blocks per b (T split).
// ---------------------------------------------------------------------------
__global__ void __launch_bounds__(256, 2) qkv_kernel(
    const float* __restrict__ x,
    const float* __restrict__ dg, const float* __restrict__ db,
    const float* __restrict__ dm, const float* __restrict__ dv,
    const float* __restrict__ W,  const float* __restrict__ Wb)
{
    int b = blockIdx.x;
    int half = blockIdx.y;
    int n = b / Vv, v = b - n * Vv;
    int T0 = half * 152;
    int TL = half ? 148 : 152;
    extern __shared__ float sm[];
    float* xs = sm;             // 64*152
    float* Wt = xs + 64 * 152;  // 12288  Wt[c*192+o] = W[o*64+c]
    float* sc = Wt + 12288;     // 64
    float* bi = sc + 64;        // 64
    int tid = threadIdx.x;

    if (tid < 64) {
        int idx = tid * Vv + v;
        float s = dg[idx] * rsqrtf(dv[idx] + 1e-5f);
        sc[tid] = s;
        bi[tid] = db[idx] - dm[idx] * s;
    }
    for (int i = tid; i < 192 * 64; i += 256) {
        int c = i / 192, o = i - c * 192;
        Wt[i] = W[o * 64 + c];
    }
    __syncthreads();

    const float* xb = x + ((size_t)n * Cc) * Tt * Vv + v;
    for (int i = tid; i < 64 * TL; i += 256) {
        int c = i / TL, tt = i - c * TL;
        xs[c * 152 + tt] = xb[(size_t)(c * Tt + T0 + tt) * Vv] * sc[c] + bi[c];
    }
    __syncthreads();

    int tcols = TL >> 2;
    int ntile = 48 * tcols;
    for (int tile = tid; tile < ntile; tile += 256) {
        int og = tile / tcols, tg = tile - og * tcols;
        int o0 = og * 4, t0 = tg * 4;
        float acc[4][4] = {};
        #pragma unroll 8
        for (int c = 0; c < 64; ++c) {
            float4 w4 = *(const float4*)(Wt + c * 192 + o0);
            float4 x4 = *(const float4*)(xs + c * 152 + t0);
            float wa[4] = {w4.x, w4.y, w4.z, w4.w};
            float xa[4] = {x4.x, x4.y, x4.z, x4.w};
            #pragma unroll
            for (int i = 0; i < 4; ++i)
                #pragma unroll
                for (int j = 0; j < 4; ++j)
                    acc[i][j] += wa[i] * xa[j];
        }
        float* outp = g_qkv + ((size_t)b * QKVO + o0) * Tt + T0 + t0;
        #pragma unroll
        for (int i = 0; i < 4; ++i) {
            float bias = Wb[o0 + i];
            float scale = (o0 + i < 64) ? 0.25f : 1.0f;  // q * DKH^-0.5
            float4 r;
            r.x = (acc[i][0] + bias) * scale;
            r.y = (acc[i][1] + bias) * scale;
            r.z = (acc[i][2] + bias) * scale;
            r.w = (acc[i][3] + bias) * scale;
            *(float4*)(outp + i * Tt) = r;
        }
    }
}

// ---------------------------------------------------------------------------
// Kernel 2: attention per (b,h). Warp owns 4 t-rows; full logits strip lives
// in registers across 3 s-passes. logits[t,s]=sum_d q[d,t]*(k[d,s]+kr[d,s-t+299])
// kr window per tile is 16B-aligned because t0 % 4 == 0.
// ---------------------------------------------------------------------------
__global__ void __launch_bounds__(256, 2) attn_kernel(const float* __restrict__ key_rel)
{
    int bh = blockIdx.x;
    int b = bh >> 2, h = bh & 3;
    extern __shared__ float sm[];
    float* qs  = sm;                 // 16*304  [d][t]
    float* ks  = qs + 16 * 304;      // 16*304  [d][s]
    float* vt  = ks + 16 * 304;      // 304*16  [s][d]
    float* krs = vt + 304 * 16;      // 16*608  [d][m]

    const float* base = g_qkv + (size_t)b * QKVO * Tt;
    const float* qg = base + (h * 16) * Tt;
    const float* kg = base + (64 + h * 16) * Tt;
    const float* vg = base + (128 + h * 16) * Tt;

    int tid = threadIdx.x;
    for (int i = tid; i < 16 * 300; i += 256) {
        int d = i / 300, t = i - d * 300;
        qs[d * 304 + t] = qg[i];
        ks[d * 304 + t] = kg[i];
        vt[t * 16 + d]  = vg[i];
    }
    for (int i = tid; i < 599 * 16; i += 256) {
        int m = i >> 4, d = i & 15;
        krs[d * 608 + m] = key_rel[i];
    }
    __syncthreads();

    int warp = tid >> 5, lane = tid & 31;

    for (int g = warp; g < 75; g += 8) {
        int t0 = g * 4;
        float L[3][4][4];
        bool sv[3];
        #pragma unroll
        for (int p = 0; p < 3; ++p) {
            int s0 = p * 128 + lane * 4;
            sv[p] = (s0 < 300);
            float init = sv[p] ? 0.f : -1e30f;
            #pragma unroll
            for (int i = 0; i < 4; ++i)
                #pragma unroll
                for (int j = 0; j < 4; ++j)
                    L[p][i][j] = init;
            if (sv[p]) {
                int m0 = s0 - t0 + 299;        // >= 3, m0-3 is 16B-aligned
                const float* qp = qs + t0;
                const float* kp = ks + s0;
                const float* rp = krs + (m0 - 3);
                #pragma unroll
                for (int d = 0; d < 16; ++d) {
                    float4 q4 = *(const float4*)(qp + d * 304);
                    float4 k4 = *(const float4*)(kp + d * 304);
                    float4 ra = *(const float4*)(rp + d * 608);
                    float4 rb = *(const float4*)(rp + d * 608 + 4);
                    float qa[4] = {q4.x, q4.y, q4.z, q4.w};
                    float kk[4] = {k4.x, k4.y, k4.z, k4.w};
                    float kr[8] = {ra.x, ra.y, ra.z, ra.w, rb.x, rb.y, rb.z, rb.w};
                    #pragma unroll
                    for (int i = 0; i < 4; ++i)
                        #pragma unroll
                        for (int j = 0; j < 4; ++j) {
                            L[p][i][j] = fmaf(qa[i], kk[j], L[p][i][j]);
                            L[p][i][j] = fmaf(qa[i], kr[3 + j - i], L[p][i][j]);
                        }
                }
            }
        }

        // ---- softmax over s for each of the 4 rows ----
        #pragma unroll
        for (int i = 0; i < 4; ++i) {
            float mx = -1e30f;
            #pragma unroll
            for (int p = 0; p < 3; ++p)
                #pragma unroll
                for (int j = 0; j < 4; ++j)
                    mx = fmaxf(mx, L[p][i][j]);
            #pragma unroll
            for (int o = 16; o > 0; o >>= 1)
                mx = fmaxf(mx, __shfl_xor_sync(0xffffffffu, mx, o));
            float s = 0.f;
            #pragma unroll
            for (int p = 0; p < 3; ++p)
                #pragma unroll
                for (int j = 0; j < 4; ++j) {
                    float e = __expf(L[p][i][j] - mx);
                    L[p][i][j] = e;
                    s += e;
                }
            #pragma unroll
            for (int o = 16; o > 0; o >>= 1)
                s += __shfl_xor_sync(0xffffffffu, s, o);
            float inv = 1.f / s;
            #pragma unroll
            for (int p = 0; p < 3; ++p)
                #pragma unroll
                for (int j = 0; j < 4; ++j)
                    L[p][i][j] *= inv;
        }

        // ---- AV from register probs, d in two halves of 8 ----
        int mi = lane >> 3, md = lane & 7;
        #pragma unroll
        for (int half = 0; half < 2; ++half) {
            float acc[4][8];
            #pragma unroll
            for (int i = 0; i < 4; ++i)
                #pragma unroll
                for (int dd = 0; dd < 8; ++dd) acc[i][dd] = 0.f;

            #pragma unroll
            for (int p = 0; p < 3; ++p) {
                if (sv[p]) {
                    int s0 = p * 128 + lane * 4;
                    #pragma unroll
                    for (int j = 0; j < 4; ++j) {
                        const float* vp = vt + (s0 + j) * 16 + half * 8;
                        float4 va = *(const float4*)(vp);
                        float4 vb = *(const float4*)(vp + 4);
                        float vv[8] = {va.x, va.y, va.z, va.w, vb.x, vb.y, vb.z, vb.w};
                        #pragma unroll
                        for (int i = 0; i < 4; ++i) {
                            float wv = L[p][i][j];
                            #pragma unroll
                            for (int dd = 0; dd < 8; ++dd)
                                acc[i][dd] = fmaf(wv, vv[dd], acc[i][dd]);
                        }
                    }
                }
            }
            // butterfly reduce each of the 32 partials over all lanes
            #pragma unroll
            for (int i = 0; i < 4; ++i)
                #pragma unroll
                for (int dd = 0; dd < 8; ++dd)
                    #pragma unroll
                    for (int o = 16; o > 0; o >>= 1)
                        acc[i][dd] += __shfl_xor_sync(0xffffffffu, acc[i][dd], o);

            // lane (mi, md) writes out[t0+mi][half*8+md]
            float myval = 0.f;
            #pragma unroll
            for (int i = 0; i < 4; ++i)
                #pragma unroll
                for (int dd = 0; dd < 8; ++dd)
                    if (i == mi && dd == md) myval = acc[i][dd];
            g_attn[((size_t)b * 64 + h * 16 + half * 8 + md) * Tt + t0 + mi] = myval;
        }
    }
}

// ---------------------------------------------------------------------------
// Kernel 3: head-mix projection + skip + BN + ReLU. 2 blocks per b (T split).
// ---------------------------------------------------------------------------
__global__ void __launch_bounds__(256, 4) proj_kernel(
    const float* __restrict__ Wa, const float* __restrict__ Ba,
    const float* __restrict__ bg, const float* __restrict__ bb,
    const float* __restrict__ bm, const float* __restrict__ bv,
    const float* __restrict__ x, float* __restrict__ out)
{
    int b = blockIdx.x;
    int half = blockIdx.y;
    int n = b / Vv, v = b - n * Vv;
    int T0 = half * 152;
    int TL = half ? 148 : 152;
    extern __shared__ float sm[];
    float* as = sm;            // 64*152
    float* Wt = as + 64 * 152; // 64*64   Wt[d*64+o] = Wa[o*64+d]
    float* s2 = Wt + 4096;     // 64
    float* b2 = s2 + 64;       // 64
    int tid = threadIdx.x;

    const float* ag = g_attn + (size_t)b * 64 * Tt;
    for (int i = tid; i < 64 * TL; i += 256) {
        int d = i / TL, tt = i - d * TL;
        as[d * 152 + tt] = ag[d * Tt + T0 + tt];
    }
    for (int i = tid; i < 4096; i += 256) {
        int d = i >> 6, o = i & 63;
        Wt[i] = Wa[o * 64 + d];
    }
    if (tid < 64) {
        float s = bg[tid] * rsqrtf(bv[tid] + 1e-5f);
        s2[tid] = s;
        b2[tid] = bb[tid] - bm[tid] * s;
    }
    __syncthreads();

    const float* xb = x + ((size_t)n * Cc) * Tt * Vv + v;
    float*       ob = out + ((size_t)n * Cc) * Tt * Vv + v;

    int tcols = TL >> 2;
    int ntile = 16 * tcols;
    for (int tile = tid; tile < ntile; tile += 256) {
        int og = tile / tcols, tg = tile - og * tcols;
        int o0 = og * 4, t0 = tg * 4;
        float acc[4][4] = {};
        #pragma unroll 8
        for (int d = 0; d < 64; ++d) {
            float4 w4 = *(const float4*)(Wt + d * 64 + o0);
            float4 a4 = *(const float4*)(as + d * 152 + t0);
            float wa[4] = {w4.x, w4.y, w4.z, w4.w};
            float aa[4] = {a4.x, a4.y, a4.z, a4.w};
            #pragma unroll
            for (int i = 0; i < 4; ++i)
                #pragma unroll
                for (int j = 0; j < 4; ++j)
                    acc[i][j] += wa[i] * aa[j];
        }
        #pragma unroll
        for (int i = 0; i < 4; ++i) {
            int o = o0 + i;
            float bias = Ba[o];
            #pragma unroll
            for (int j = 0; j < 4; ++j) {
                int t = T0 + t0 + j;
                size_t gi = (size_t)(o * Tt + t) * Vv;
                float r = acc[i][j] + bias + xb[gi];
                r = r * s2[o] + b2[o];
                ob[gi] = fmaxf(r, 0.f);
            }
        }
    }
}

// ---------------------------------------------------------------------------
extern "C" void kernel_launch(void* const* d_in, const int* in_sizes, int n_in,
                              void* d_out, int out_size)
{
    const float* x       = (const float*)d_in[0];
    const float* dbn_g   = (const float*)d_in[1];
    const float* dbn_b   = (const float*)d_in[2];
    const float* dbn_m   = (const float*)d_in[3];
    const float* dbn_v   = (const float*)d_in[4];
    const float* qkv_w   = (const float*)d_in[5];
    const float* qkv_b   = (const float*)d_in[6];
    const float* key_rel = (const float*)d_in[7];
    const float* attn_w  = (const float*)d_in[8];
    const float* attn_b  = (const float*)d_in[9];
    const float* bn_g    = (const float*)d_in[10];
    const float* bn_b    = (const float*)d_in[11];
    const float* bn_m    = (const float*)d_in[12];
    const float* bn_v    = (const float*)d_in[13];
    float* out = (float*)d_out;

    const int SM1 = (64 * 152 + 12288 + 128) * 4;            //  88,576
    const int SM2 = (16 * 304 * 2 + 304 * 16 + 16 * 608) * 4; // 97,280
    const int SM3 = (64 * 152 + 4096 + 128) * 4;             //  55,808

    cudaFuncSetAttribute(qkv_kernel,  cudaFuncAttributeMaxDynamicSharedMemorySize, SM1);
    cudaFuncSetAttribute(attn_kernel, cudaFuncAttributeMaxDynamicSharedMemorySize, SM2);
    cudaFuncSetAttribute(proj_kernel, cudaFuncAttributeMaxDynamicSharedMemorySize, SM3);

    qkv_kernel<<<dim3(Bb, 2), 256, SM1>>>(x, dbn_g, dbn_b, dbn_m, dbn_v, qkv_w, qkv_b);
    attn_kernel<<<Bb * NHh, 256, SM2>>>(key_rel);
    proj_kernel<<<dim3(Bb, 2), 256, SM3>>>(attn_w, attn_b, bn_g, bn_b, bn_m, bn_v, x, out);
}

// round 3
// speedup vs baseline: 1.5727x; 1.5727x over previous
#include <cuda_runtime.h>
#include <cuda_bf16.h>
#include <math.h>

#define Nn 16
#define Cc 64
#define Tt 300
#define Vv 25
#define NHh 4
#define Bb (Nn*Vv)          // 400
#define QKVO 192            // 2*DK+DV

// Scratch (static device memory; no runtime allocation)
__device__ float g_qkv[(size_t)Bb * QKVO * Tt];    // 23,040,000 floats
__device__ float g_attn[(size_t)Bb * 64 * Tt];     //  7,680,000 floats

// ---------------------------------------------------------------------------
// Kernel 1: fused data_bn (eval) + 1x1 qkv conv. 2 blocks per b (T split).
// ---------------------------------------------------------------------------
__global__ void __launch_bounds__(256, 2) qkv_kernel(
    const float* __restrict__ x,
    const float* __restrict__ dg, const float* __restrict__ db,
    const float* __restrict__ dm, const float* __restrict__ dv,
    const float* __restrict__ W,  const float* __restrict__ Wb)
{
    int b = blockIdx.x;
    int half = blockIdx.y;
    int n = b / Vv, v = b - n * Vv;
    int T0 = half * 152;
    int TL = half ? 148 : 152;
    extern __shared__ float sm[];
    float* xs = sm;             // 64*152
    float* Wt = xs + 64 * 152;  // 12288  Wt[c*192+o] = W[o*64+c]
    float* sc = Wt + 12288;     // 64
    float* bi = sc + 64;        // 64
    int tid = threadIdx.x;

    if (tid < 64) {
        int idx = tid * Vv + v;
        float s = dg[idx] * rsqrtf(dv[idx] + 1e-5f);
        sc[tid] = s;
        bi[tid] = db[idx] - dm[idx] * s;
    }
    for (int i = tid; i < 192 * 64; i += 256) {
        int c = i / 192, o = i - c * 192;
        Wt[i] = W[o * 64 + c];
    }
    __syncthreads();

    const float* xb = x + ((size_t)n * Cc) * Tt * Vv + v;
    for (int i = tid; i < 64 * TL; i += 256) {
        int c = i / TL, tt = i - c * TL;
        xs[c * 152 + tt] = xb[(size_t)(c * Tt + T0 + tt) * Vv] * sc[c] + bi[c];
    }
    __syncthreads();

    int tcols = TL >> 2;
    int ntile = 48 * tcols;
    for (int tile = tid; tile < ntile; tile += 256) {
        int og = tile / tcols, tg = tile - og * tcols;
        int o0 = og * 4, t0 = tg * 4;
        float acc[4][4] = {};
        #pragma unroll 8
        for (int c = 0; c < 64; ++c) {
            float4 w4 = *(const float4*)(Wt + c * 192 + o0);
            float4 x4 = *(const float4*)(xs + c * 152 + t0);
            float wa[4] = {w4.x, w4.y, w4.z, w4.w};
            float xa[4] = {x4.x, x4.y, x4.z, x4.w};
            #pragma unroll
            for (int i = 0; i < 4; ++i)
                #pragma unroll
                for (int j = 0; j < 4; ++j)
                    acc[i][j] += wa[i] * xa[j];
        }
        float* outp = g_qkv + ((size_t)b * QKVO + o0) * Tt + T0 + t0;
        #pragma unroll
        for (int i = 0; i < 4; ++i) {
            float bias = Wb[o0 + i];
            float scale = (o0 + i < 64) ? 0.25f : 1.0f;  // q * DKH^-0.5
            float4 r;
            r.x = (acc[i][0] + bias) * scale;
            r.y = (acc[i][1] + bias) * scale;
            r.z = (acc[i][2] + bias) * scale;
            r.w = (acc[i][3] + bias) * scale;
            *(float4*)(outp + i * Tt) = r;
        }
    }
}

// ---------------------------------------------------------------------------
// Kernel 2: attention per (b,h). Warp owns a 4-row t-tile; 4x300 logits strip
// in registers across 3 s-passes of 128. AV via per-warp SMEM prob strip:
// no shuffles, 2 accumulators per lane. q read straight from global (used once).
// ---------------------------------------------------------------------------
#define KST 300   // ks row stride
#define VST 316   // vs row stride (banks 28*d mod 32 -> conflict-free)
#define RST 600   // krs row stride
#define PST 132   // prob strip row stride (banks 4*i -> disjoint spans)

__global__ void __launch_bounds__(256, 2) attn_kernel(const float* __restrict__ key_rel)
{
    int bh = blockIdx.x;
    int b = bh >> 2, h = bh & 3;
    extern __shared__ float sm[];
    float* ks   = sm;                  // 16*300  [d][s]
    float* vs   = ks + 16 * KST;       // 16*316  [d][s]
    float* krs  = vs + 16 * VST;       // 16*600  [d][m]
    float* strp = krs + 16 * RST;      // 8 warps * 4*132

    const float* base = g_qkv + (size_t)b * QKVO * Tt;
    const float* qg = base + (h * 16) * Tt;
    const float* kg = base + (64 + h * 16) * Tt;
    const float* vg = base + (128 + h * 16) * Tt;

    int tid = threadIdx.x;
    // k: contiguous copy (row stride == 300)
    for (int i = tid; i < 1200; i += 256)
        ((float4*)ks)[i] = ((const float4*)kg)[i];
    // v: re-stride to 316
    #pragma unroll
    for (int d = 0; d < 16; ++d)
        for (int t = tid; t < 300; t += 256)
            vs[d * VST + t] = vg[d * 300 + t];
    // key_rel transpose: krs[d][m] = key_rel[m*16+d]
    for (int i = tid; i < 599 * 16; i += 256) {
        int m = i >> 4, d = i & 15;
        krs[d * RST + m] = key_rel[i];
    }
    __syncthreads();

    int warp = tid >> 5, lane = tid & 31;
    float* stw = strp + warp * 4 * PST;
    int li = lane >> 3, ld = lane & 7;       // AV lane mapping (t-row, d)

    for (int g = warp; g < 75; g += 8) {
        int t0 = g * 4;
        float L[3][4][4];
        #pragma unroll
        for (int p = 0; p < 3; ++p)
            #pragma unroll
            for (int i = 0; i < 4; ++i)
                #pragma unroll
                for (int j = 0; j < 4; ++j)
                    L[p][i][j] = -1e30f;

        bool v2 = (lane < 11);   // p=2 valid lanes (s0 = 256+lane*4 < 300)
        #pragma unroll
        for (int p = 0; p < 3; ++p) {
            if (p < 2 || v2) {
                #pragma unroll
                for (int i = 0; i < 4; ++i)
                    #pragma unroll
                    for (int j = 0; j < 4; ++j)
                        L[p][i][j] = 0.f;
            }
        }

        // ---- QK + rel ----
        #pragma unroll
        for (int d = 0; d < 16; ++d) {
            float4 q4 = __ldg((const float4*)(qg + d * 300 + t0));
            float qa[4] = {q4.x, q4.y, q4.z, q4.w};
            #pragma unroll
            for (int p = 0; p < 3; ++p) {
                if (p < 2 || v2) {
                    int s0 = p * 128 + lane * 4;
                    int m0 = s0 - t0 + 296;           // m0 = (s0 - t0 + 299) - 3, 16B-aligned
                    float4 k4 = *(const float4*)(ks + d * KST + s0);
                    float4 ra = *(const float4*)(krs + d * RST + m0);
                    float4 rb = *(const float4*)(krs + d * RST + m0 + 4);
                    float kk[4] = {k4.x, k4.y, k4.z, k4.w};
                    float kr[8] = {ra.x, ra.y, ra.z, ra.w, rb.x, rb.y, rb.z, rb.w};
                    #pragma unroll
                    for (int i = 0; i < 4; ++i)
                        #pragma unroll
                        for (int j = 0; j < 4; ++j) {
                            L[p][i][j] = fmaf(qa[i], kk[j], L[p][i][j]);
                            L[p][i][j] = fmaf(qa[i], kr[3 + j - i], L[p][i][j]);
                        }
                }
            }
        }

        // ---- softmax over s for each of the 4 rows ----
        #pragma unroll
        for (int i = 0; i < 4; ++i) {
            float mx = -1e30f;
            #pragma unroll
            for (int p = 0; p < 3; ++p)
                #pragma unroll
                for (int j = 0; j < 4; ++j)
                    mx = fmaxf(mx, L[p][i][j]);
            #pragma unroll
            for (int o = 16; o > 0; o >>= 1)
                mx = fmaxf(mx, __shfl_xor_sync(0xffffffffu, mx, o));
            float s = 0.f;
            #pragma unroll
            for (int p = 0; p < 3; ++p)
                #pragma unroll
                for (int j = 0; j < 4; ++j) {
                    float e = __expf(L[p][i][j] - mx);
                    L[p][i][j] = e;
                    s += e;
                }
            #pragma unroll
            for (int o = 16; o > 0; o >>= 1)
                s += __shfl_xor_sync(0xffffffffu, s, o);
            float inv = 1.f / s;
            #pragma unroll
            for (int p = 0; p < 3; ++p)
                #pragma unroll
                for (int j = 0; j < 4; ++j)
                    L[p][i][j] *= inv;
        }

        // ---- AV: per s-chunk, stage probs in warp-private strip, dense dots ----
        float acc0 = 0.f, acc1 = 0.f;
        #pragma unroll
        for (int p = 0; p < 3; ++p) {
            __syncwarp();
            if (p < 2 || v2) {
                #pragma unroll
                for (int i = 0; i < 4; ++i) {
                    float4 w4 = make_float4(L[p][i][0], L[p][i][1], L[p][i][2], L[p][i][3]);
                    *(float4*)(stw + i * PST + lane * 4) = w4;
                }
            }
            __syncwarp();
            const int iters = (p < 2) ? 32 : 11;   // last chunk: 44 valid s
            const float* va = vs + ld * VST + p * 128;
            const float* vb = vs + (ld + 8) * VST + p * 128;
            const float* pw = stw + li * PST;
            #pragma unroll 4
            for (int s4 = 0; s4 < iters; ++s4) {
                float4 pr = *(const float4*)(pw + s4 * 4);
                float4 a4 = *(const float4*)(va + s4 * 4);
                float4 b4 = *(const float4*)(vb + s4 * 4);
                acc0 = fmaf(pr.x, a4.x, acc0); acc0 = fmaf(pr.y, a4.y, acc0);
                acc0 = fmaf(pr.z, a4.z, acc0); acc0 = fmaf(pr.w, a4.w, acc0);
                acc1 = fmaf(pr.x, b4.x, acc1); acc1 = fmaf(pr.y, b4.y, acc1);
                acc1 = fmaf(pr.z, b4.z, acc1); acc1 = fmaf(pr.w, b4.w, acc1);
            }
        }
        float* ob = g_attn + ((size_t)b * 64 + h * 16) * Tt + t0 + li;
        ob[(size_t)ld * Tt] = acc0;
        ob[(size_t)(ld + 8) * Tt] = acc1;
    }
}

// ---------------------------------------------------------------------------
// Kernel 3: head-mix projection + skip + BN + ReLU. 2 blocks per b (T split).
// ---------------------------------------------------------------------------
__global__ void __launch_bounds__(256, 4) proj_kernel(
    const float* __restrict__ Wa, const float* __restrict__ Ba,
    const float* __restrict__ bg, const float* __restrict__ bb,
    const float* __restrict__ bm, const float* __restrict__ bv,
    const float* __restrict__ x, float* __restrict__ out)
{
    int b = blockIdx.x;
    int half = blockIdx.y;
    int n = b / Vv, v = b - n * Vv;
    int T0 = half * 152;
    int TL = half ? 148 : 152;
    extern __shared__ float sm[];
    float* as = sm;            // 64*152
    float* Wt = as + 64 * 152; // 64*64   Wt[d*64+o] = Wa[o*64+d]
    float* s2 = Wt + 4096;     // 64
    float* b2 = s2 + 64;       // 64
    int tid = threadIdx.x;

    const float* ag = g_attn + (size_t)b * 64 * Tt;
    for (int i = tid; i < 64 * TL; i += 256) {
        int d = i / TL, tt = i - d * TL;
        as[d * 152 + tt] = ag[d * Tt + T0 + tt];
    }
    for (int i = tid; i < 4096; i += 256) {
        int d = i >> 6, o = i & 63;
        Wt[i] = Wa[o * 64 + d];
    }
    if (tid < 64) {
        float s = bg[tid] * rsqrtf(bv[tid] + 1e-5f);
        s2[tid] = s;
        b2[tid] = bb[tid] - bm[tid] * s;
    }
    __syncthreads();

    const float* xb = x + ((size_t)n * Cc) * Tt * Vv + v;
    float*       ob = out + ((size_t)n * Cc) * Tt * Vv + v;

    int tcols = TL >> 2;
    int ntile = 16 * tcols;
    for (int tile = tid; tile < ntile; tile += 256) {
        int og = tile / tcols, tg = tile - og * tcols;
        int o0 = og * 4, t0 = tg * 4;
        float acc[4][4] = {};
        #pragma unroll 8
        for (int d = 0; d < 64; ++d) {
            float4 w4 = *(const float4*)(Wt + d * 64 + o0);
            float4 a4 = *(const float4*)(as + d * 152 + t0);
            float wa[4] = {w4.x, w4.y, w4.z, w4.w};
            float aa[4] = {a4.x, a4.y, a4.z, a4.w};
            #pragma unroll
            for (int i = 0; i < 4; ++i)
                #pragma unroll
                for (int j = 0; j < 4; ++j)
                    acc[i][j] += wa[i] * aa[j];
        }
        #pragma unroll
        for (int i = 0; i < 4; ++i) {
            int o = o0 + i;
            float bias = Ba[o];
            #pragma unroll
            for (int j = 0; j < 4; ++j) {
                int t = T0 + t0 + j;
                size_t gi = (size_t)(o * Tt + t) * Vv;
                float r = acc[i][j] + bias + xb[gi];
                r = r * s2[o] + b2[o];
                ob[gi] = fmaxf(r, 0.f);
            }
        }
    }
}

// ---------------------------------------------------------------------------
extern "C" void kernel_launch(void* const* d_in, const int* in_sizes, int n_in,
                              void* d_out, int out_size)
{
    const float* x       = (const float*)d_in[0];
    const float* dbn_g   = (const float*)d_in[1];
    const float* dbn_b   = (const float*)d_in[2];
    const float* dbn_m   = (const float*)d_in[3];
    const float* dbn_v   = (const float*)d_in[4];
    const float* qkv_w   = (const float*)d_in[5];
    const float* qkv_b   = (const float*)d_in[6];
    const float* key_rel = (const float*)d_in[7];
    const float* attn_w  = (const float*)d_in[8];
    const float* attn_b  = (const float*)d_in[9];
    const float* bn_g    = (const float*)d_in[10];
    const float* bn_b    = (const float*)d_in[11];
    const float* bn_m    = (const float*)d_in[12];
    const float* bn_v    = (const float*)d_in[13];
    float* out = (float*)d_out;

    const int SM1 = (64 * 152 + 12288 + 128) * 4;                    //  88,576
    const int SM2 = (16 * KST + 16 * VST + 16 * RST + 8 * 4 * PST) * 4; // 94,720
    const int SM3 = (64 * 152 + 4096 + 128) * 4;                     //  55,808

    cudaFuncSetAttribute(qkv_kernel,  cudaFuncAttributeMaxDynamicSharedMemorySize, SM1);
    cudaFuncSetAttribute(attn_kernel, cudaFuncAttributeMaxDynamicSharedMemorySize, SM2);
    cudaFuncSetAttribute(proj_kernel, cudaFuncAttributeMaxDynamicSharedMemorySize, SM3);

    qkv_kernel<<<dim3(Bb, 2), 256, SM1>>>(x, dbn_g, dbn_b, dbn_m, dbn_v, qkv_w, qkv_b);
    attn_kernel<<<Bb * NHh, 256, SM2>>>(key_rel);
    proj_kernel<<<dim3(Bb, 2), 256, SM3>>>(attn_w, attn_b, bn_g, bn_b, bn_m, bn_v, x, out);
}

// round 4
// speedup vs baseline: 1.6433x; 1.0449x over previous
#include <cuda_runtime.h>
#include <cuda_bf16.h>
#include <math.h>

#define Nn 16
#define Cc 64
#define Tt 300
#define Vv 25
#define NHh 4
#define Bb (Nn*Vv)          // 400
#define QKVO 192            // 2*DK+DV

__device__ float g_qkv[(size_t)Bb * QKVO * Tt];
__device__ float g_attn[(size_t)Bb * 64 * Tt];

// ---- packed fp32 helpers (FFMA2 / FMUL2 are PTX-only on sm_103a) ----
__device__ __forceinline__ float2 ffma2(float2 a, float2 b, float2 c) {
    unsigned long long A = *(unsigned long long*)&a;
    unsigned long long B = *(unsigned long long*)&b;
    unsigned long long C = *(unsigned long long*)&c;
    unsigned long long D;
    asm("fma.rn.f32x2 %0, %1, %2, %3;" : "=l"(D) : "l"(A), "l"(B), "l"(C));
    return *(float2*)&D;
}
__device__ __forceinline__ float2 fmul2(float2 a, float2 b) {
    unsigned long long A = *(unsigned long long*)&a;
    unsigned long long B = *(unsigned long long*)&b;
    unsigned long long D;
    asm("mul.rn.f32x2 %0, %1, %2;" : "=l"(D) : "l"(A), "l"(B));
    return *(float2*)&D;
}

// ---------------------------------------------------------------------------
// Kernel 1: fused data_bn (eval) + 1x1 qkv conv. 3 blocks per b (T split of 100).
// ---------------------------------------------------------------------------
__global__ void __launch_bounds__(256, 3) qkv_kernel(
    const float* __restrict__ x,
    const float* __restrict__ dg, const float* __restrict__ db,
    const float* __restrict__ dm, const float* __restrict__ dv,
    const float* __restrict__ W,  const float* __restrict__ Wb)
{
    int b = blockIdx.x;
    int T0 = blockIdx.y * 100;
    int n = b / Vv, v = b - n * Vv;
    extern __shared__ float sm[];
    float* xs = sm;             // 64*100
    float* Wt = xs + 6400;      // 12288  Wt[c*192+o] = W[o*64+c]
    float* sc = Wt + 12288;     // 64
    float* bi = sc + 64;        // 64
    int tid = threadIdx.x;

    if (tid < 64) {
        int idx = tid * Vv + v;
        float s = dg[idx] * rsqrtf(dv[idx] + 1e-5f);
        sc[tid] = s;
        bi[tid] = db[idx] - dm[idx] * s;
    }
    for (int i = tid; i < 192 * 64; i += 256) {
        int c = i / 192, o = i - c * 192;
        Wt[i] = W[o * 64 + c];
    }
    __syncthreads();

    const float* xb = x + ((size_t)n * Cc) * Tt * Vv + v;
    for (int i = tid; i < 64 * 100; i += 256) {
        int c = i / 100, tt = i - c * 100;
        xs[i] = xb[(size_t)(c * Tt + T0 + tt) * Vv] * sc[c] + bi[c];
    }
    __syncthreads();

    // 192x100 outputs in 4x4 tiles: 48*25 = 1200 tiles
    for (int tile = tid; tile < 1200; tile += 256) {
        int og = tile / 25, tg = tile - og * 25;
        int o0 = og * 4, t0 = tg * 4;
        float2 acc[4][2] = {};
        #pragma unroll 8
        for (int c = 0; c < 64; ++c) {
            float4 w4 = *(const float4*)(Wt + c * 192 + o0);
            float4 x4 = *(const float4*)(xs + c * 100 + t0);
            float2 x01 = make_float2(x4.x, x4.y);
            float2 x23 = make_float2(x4.z, x4.w);
            float2 w0 = make_float2(w4.x, w4.x);
            float2 w1 = make_float2(w4.y, w4.y);
            float2 w2 = make_float2(w4.z, w4.z);
            float2 w3 = make_float2(w4.w, w4.w);
            acc[0][0] = ffma2(w0, x01, acc[0][0]); acc[0][1] = ffma2(w0, x23, acc[0][1]);
            acc[1][0] = ffma2(w1, x01, acc[1][0]); acc[1][1] = ffma2(w1, x23, acc[1][1]);
            acc[2][0] = ffma2(w2, x01, acc[2][0]); acc[2][1] = ffma2(w2, x23, acc[2][1]);
            acc[3][0] = ffma2(w3, x01, acc[3][0]); acc[3][1] = ffma2(w3, x23, acc[3][1]);
        }
        float* outp = g_qkv + ((size_t)b * QKVO + o0) * Tt + T0 + t0;
        #pragma unroll
        for (int i = 0; i < 4; ++i) {
            float bias = Wb[o0 + i];
            float scale = (o0 + i < 64) ? 0.25f : 1.0f;  // q * DKH^-0.5
            float4 r;
            r.x = (acc[i][0].x + bias) * scale;
            r.y = (acc[i][0].y + bias) * scale;
            r.z = (acc[i][1].x + bias) * scale;
            r.w = (acc[i][1].y + bias) * scale;
            *(float4*)(outp + i * Tt) = r;
        }
    }
}

// ---------------------------------------------------------------------------
// Kernel 2: attention per (b,h). Warp owns 4 t-rows; logits strip in packed
// f32x2 registers across 3 s-passes. QK, rel and AV all via fma.rn.f32x2.
// ---------------------------------------------------------------------------
#define KST 300   // ks row stride
#define VST 316   // vs row stride
#define RST 600   // krs row stride
#define PST 132   // prob strip row stride

__global__ void __launch_bounds__(256, 2) attn_kernel(const float* __restrict__ key_rel)
{
    int bh = blockIdx.x;
    int b = bh >> 2, h = bh & 3;
    extern __shared__ float sm[];
    float* ks   = sm;                  // 16*300  [d][s]
    float* vs   = ks + 16 * KST;       // 16*316  [d][s]
    float* krs  = vs + 16 * VST;       // 16*600  [d][m]
    float* strp = krs + 16 * RST;      // 8 warps * 4*132

    const float* base = g_qkv + (size_t)b * QKVO * Tt;
    const float* qg = base + (h * 16) * Tt;
    const float* kg = base + (64 + h * 16) * Tt;
    const float* vg = base + (128 + h * 16) * Tt;

    int tid = threadIdx.x;
    for (int i = tid; i < 1200; i += 256)
        ((float4*)ks)[i] = ((const float4*)kg)[i];
    #pragma unroll
    for (int d = 0; d < 16; ++d)
        for (int t = tid; t < 300; t += 256)
            vs[d * VST + t] = vg[d * 300 + t];
    for (int i = tid; i < 599 * 16; i += 256) {
        int m = i >> 4, d = i & 15;
        krs[d * RST + m] = key_rel[i];
    }
    __syncthreads();

    int warp = tid >> 5, lane = tid & 31;
    float* stw = strp + warp * 4 * PST;
    int li = lane >> 3, ld = lane & 7;

    for (int g = warp; g < 75; g += 8) {
        int t0 = g * 4;
        float2 L[3][4][2];   // [p][i][jpair]
        bool v2 = (lane < 11);
        #pragma unroll
        for (int p = 0; p < 3; ++p) {
            float init = (p < 2 || v2) ? 0.f : -1e30f;
            #pragma unroll
            for (int i = 0; i < 4; ++i) {
                L[p][i][0] = make_float2(init, init);
                L[p][i][1] = make_float2(init, init);
            }
        }

        // ---- QK + rel (packed over s-pairs) ----
        #pragma unroll
        for (int d = 0; d < 16; ++d) {
            float4 q4 = __ldg((const float4*)(qg + d * 300 + t0));
            float2 qd[4] = { make_float2(q4.x, q4.x), make_float2(q4.y, q4.y),
                             make_float2(q4.z, q4.z), make_float2(q4.w, q4.w) };
            #pragma unroll
            for (int p = 0; p < 3; ++p) {
                if (p < 2 || v2) {
                    int s0 = p * 128 + lane * 4;
                    int m0 = s0 - t0 + 296;             // 16B-aligned base (kr[ -3 ])
                    float4 k4 = *(const float4*)(ks + d * KST + s0);
                    float4 ra = *(const float4*)(krs + d * RST + m0);
                    float4 rb = *(const float4*)(krs + d * RST + m0 + 4);
                    float2 k01 = make_float2(k4.x, k4.y), k23 = make_float2(k4.z, k4.w);
                    float2 r01 = make_float2(ra.x, ra.y), r23 = make_float2(ra.z, ra.w);
                    float2 r45 = make_float2(rb.x, rb.y);
                    float2 r12 = make_float2(ra.y, ra.z);
                    float2 r34 = make_float2(ra.w, rb.x);
                    float2 r56 = make_float2(rb.y, rb.z);
                    // k term
                    L[p][0][0] = ffma2(qd[0], k01, L[p][0][0]); L[p][0][1] = ffma2(qd[0], k23, L[p][0][1]);
                    L[p][1][0] = ffma2(qd[1], k01, L[p][1][0]); L[p][1][1] = ffma2(qd[1], k23, L[p][1][1]);
                    L[p][2][0] = ffma2(qd[2], k01, L[p][2][0]); L[p][2][1] = ffma2(qd[2], k23, L[p][2][1]);
                    L[p][3][0] = ffma2(qd[3], k01, L[p][3][0]); L[p][3][1] = ffma2(qd[3], k23, L[p][3][1]);
                    // rel term: kr[3 + j - i] relative to ra.x = kr[0]
                    L[p][0][0] = ffma2(qd[0], r34, L[p][0][0]); L[p][0][1] = ffma2(qd[0], r56, L[p][0][1]);
                    L[p][1][0] = ffma2(qd[1], r23, L[p][1][0]); L[p][1][1] = ffma2(qd[1], r45, L[p][1][1]);
                    L[p][2][0] = ffma2(qd[2], r12, L[p][2][0]); L[p][2][1] = ffma2(qd[2], r34, L[p][2][1]);
                    L[p][3][0] = ffma2(qd[3], r01, L[p][3][0]); L[p][3][1] = ffma2(qd[3], r23, L[p][3][1]);
                }
            }
        }

        // ---- softmax per row ----
        #pragma unroll
        for (int i = 0; i < 4; ++i) {
            float mx = -1e30f;
            #pragma unroll
            for (int p = 0; p < 3; ++p)
                #pragma unroll
                for (int jp = 0; jp < 2; ++jp)
                    mx = fmaxf(mx, fmaxf(L[p][i][jp].x, L[p][i][jp].y));
            #pragma unroll
            for (int o = 16; o > 0; o >>= 1)
                mx = fmaxf(mx, __shfl_xor_sync(0xffffffffu, mx, o));
            float s = 0.f;
            #pragma unroll
            for (int p = 0; p < 3; ++p)
                #pragma unroll
                for (int jp = 0; jp < 2; ++jp) {
                    float ex = __expf(L[p][i][jp].x - mx);
                    float ey = __expf(L[p][i][jp].y - mx);
                    L[p][i][jp] = make_float2(ex, ey);
                    s += ex + ey;
                }
            #pragma unroll
            for (int o = 16; o > 0; o >>= 1)
                s += __shfl_xor_sync(0xffffffffu, s, o);
            float inv = 1.f / s;
            float2 inv2 = make_float2(inv, inv);
            #pragma unroll
            for (int p = 0; p < 3; ++p)
                #pragma unroll
                for (int jp = 0; jp < 2; ++jp)
                    L[p][i][jp] = fmul2(L[p][i][jp], inv2);
        }

        // ---- AV via warp-private prob strip (packed) ----
        float2 acc0 = make_float2(0.f, 0.f), acc1 = make_float2(0.f, 0.f);
        #pragma unroll
        for (int p = 0; p < 3; ++p) {
            __syncwarp();
            if (p < 2 || v2) {
                #pragma unroll
                for (int i = 0; i < 4; ++i) {
                    float4 w4 = make_float4(L[p][i][0].x, L[p][i][0].y,
                                            L[p][i][1].x, L[p][i][1].y);
                    *(float4*)(stw + i * PST + lane * 4) = w4;
                }
            }
            __syncwarp();
            const int iters = (p < 2) ? 32 : 11;
            const float* va = vs + ld * VST + p * 128;
            const float* vb = vs + (ld + 8) * VST + p * 128;
            const float* pw = stw + li * PST;
            #pragma unroll 4
            for (int s4 = 0; s4 < iters; ++s4) {
                float4 pr = *(const float4*)(pw + s4 * 4);
                float4 a4 = *(const float4*)(va + s4 * 4);
                float4 b4 = *(const float4*)(vb + s4 * 4);
                acc0 = ffma2(make_float2(pr.x, pr.y), make_float2(a4.x, a4.y), acc0);
                acc0 = ffma2(make_float2(pr.z, pr.w), make_float2(a4.z, a4.w), acc0);
                acc1 = ffma2(make_float2(pr.x, pr.y), make_float2(b4.x, b4.y), acc1);
                acc1 = ffma2(make_float2(pr.z, pr.w), make_float2(b4.z, b4.w), acc1);
            }
        }
        float* ob = g_attn + ((size_t)b * 64 + h * 16) * Tt + t0 + li;
        ob[(size_t)ld * Tt] = acc0.x + acc0.y;
        ob[(size_t)(ld + 8) * Tt] = acc1.x + acc1.y;
    }
}

// ---------------------------------------------------------------------------
// Kernel 3: head-mix projection + skip + BN + ReLU. 2 blocks per b (T split).
// ---------------------------------------------------------------------------
__global__ void __launch_bounds__(256, 4) proj_kernel(
    const float* __restrict__ Wa, const float* __restrict__ Ba,
    const float* __restrict__ bg, const float* __restrict__ bb,
    const float* __restrict__ bm, const float* __restrict__ bv,
    const float* __restrict__ x, float* __restrict__ out)
{
    int b = blockIdx.x;
    int half = blockIdx.y;
    int n = b / Vv, v = b - n * Vv;
    int T0 = half * 152;
    int TL = half ? 148 : 152;
    extern __shared__ float sm[];
    float* as = sm;            // 64*152
    float* Wt = as + 64 * 152; // 64*64   Wt[d*64+o] = Wa[o*64+d]
    float* s2 = Wt + 4096;     // 64
    float* b2 = s2 + 64;       // 64
    int tid = threadIdx.x;

    const float* ag = g_attn + (size_t)b * 64 * Tt;
    for (int i = tid; i < 64 * TL; i += 256) {
        int d = i / TL, tt = i - d * TL;
        as[d * 152 + tt] = ag[d * Tt + T0 + tt];
    }
    for (int i = tid; i < 4096; i += 256) {
        int d = i >> 6, o = i & 63;
        Wt[i] = Wa[o * 64 + d];
    }
    if (tid < 64) {
        float s = bg[tid] * rsqrtf(bv[tid] + 1e-5f);
        s2[tid] = s;
        b2[tid] = bb[tid] - bm[tid] * s;
    }
    __syncthreads();

    const float* xb = x + ((size_t)n * Cc) * Tt * Vv + v;
    float*       ob = out + ((size_t)n * Cc) * Tt * Vv + v;

    int tcols = TL >> 2;
    int ntile = 16 * tcols;
    for (int tile = tid; tile < ntile; tile += 256) {
        int og = tile / tcols, tg = tile - og * tcols;
        int o0 = og * 4, t0 = tg * 4;
        float2 acc[4][2] = {};
        #pragma unroll 8
        for (int d = 0; d < 64; ++d) {
            float4 w4 = *(const float4*)(Wt + d * 64 + o0);
            float4 a4 = *(const float4*)(as + d * 152 + t0);
            float2 a01 = make_float2(a4.x, a4.y);
            float2 a23 = make_float2(a4.z, a4.w);
            float2 w0 = make_float2(w4.x, w4.x);
            float2 w1 = make_float2(w4.y, w4.y);
            float2 w2 = make_float2(w4.z, w4.z);
            float2 w3 = make_float2(w4.w, w4.w);
            acc[0][0] = ffma2(w0, a01, acc[0][0]); acc[0][1] = ffma2(w0, a23, acc[0][1]);
            acc[1][0] = ffma2(w1, a01, acc[1][0]); acc[1][1] = ffma2(w1, a23, acc[1][1]);
            acc[2][0] = ffma2(w2, a01, acc[2][0]); acc[2][1] = ffma2(w2, a23, acc[2][1]);
            acc[3][0] = ffma2(w3, a01, acc[3][0]); acc[3][1] = ffma2(w3, a23, acc[3][1]);
        }
        #pragma unroll
        for (int i = 0; i < 4; ++i) {
            int o = o0 + i;
            float bias = Ba[o];
            float av[4] = {acc[i][0].x, acc[i][0].y, acc[i][1].x, acc[i][1].y};
            #pragma unroll
            for (int j = 0; j < 4; ++j) {
                int t = T0 + t0 + j;
                size_t gi = (size_t)(o * Tt + t) * Vv;
                float r = av[j] + bias + xb[gi];
                r = r * s2[o] + b2[o];
                ob[gi] = fmaxf(r, 0.f);
            }
        }
    }
}

// ---------------------------------------------------------------------------
extern "C" void kernel_launch(void* const* d_in, const int* in_sizes, int n_in,
                              void* d_out, int out_size)
{
    const float* x       = (const float*)d_in[0];
    const float* dbn_g   = (const float*)d_in[1];
    const float* dbn_b   = (const float*)d_in[2];
    const float* dbn_m   = (const float*)d_in[3];
    const float* dbn_v   = (const float*)d_in[4];
    const float* qkv_w   = (const float*)d_in[5];
    const float* qkv_b   = (const float*)d_in[6];
    const float* key_rel = (const float*)d_in[7];
    const float* attn_w  = (const float*)d_in[8];
    const float* attn_b  = (const float*)d_in[9];
    const float* bn_g    = (const float*)d_in[10];
    const float* bn_b    = (const float*)d_in[11];
    const float* bn_m    = (const float*)d_in[12];
    const float* bn_v    = (const float*)d_in[13];
    float* out = (float*)d_out;

    const int SM1 = (6400 + 12288 + 128) * 4;                           // 75,264
    const int SM2 = (16 * KST + 16 * VST + 16 * RST + 8 * 4 * PST) * 4; // 94,720
    const int SM3 = (64 * 152 + 4096 + 128) * 4;                        // 55,808

    cudaFuncSetAttribute(qkv_kernel,  cudaFuncAttributeMaxDynamicSharedMemorySize, SM1);
    cudaFuncSetAttribute(attn_kernel, cudaFuncAttributeMaxDynamicSharedMemorySize, SM2);
    cudaFuncSetAttribute(proj_kernel, cudaFuncAttributeMaxDynamicSharedMemorySize, SM3);

    qkv_kernel<<<dim3(Bb, 3), 256, SM1>>>(x, dbn_g, dbn_b, dbn_m, dbn_v, qkv_w, qkv_b);
    attn_kernel<<<Bb * NHh, 256, SM2>>>(key_rel);
    proj_kernel<<<dim3(Bb, 2), 256, SM3>>>(attn_w, attn_b, bn_g, bn_b, bn_m, bn_v, x, out);
}

// round 5
// speedup vs baseline: 1.7587x; 1.0702x over previous
#include <cuda_runtime.h>
#include <cuda_bf16.h>
#include <math.h>

#define Nn 16
#define Cc 64
#define Tt 300
#define Vv 25
#define NHh 4
#define Bb (Nn*Vv)          // 400
#define QKVO 192            // 2*DK+DV

__device__ float g_qkv[(size_t)Bb * QKVO * Tt];
__device__ float g_attn[(size_t)Bb * 64 * Tt];

// ---- packed fp32 helpers (FFMA2 / FMUL2 are PTX-only on sm_103a) ----
__device__ __forceinline__ float2 ffma2(float2 a, float2 b, float2 c) {
    unsigned long long A = *(unsigned long long*)&a;
    unsigned long long B = *(unsigned long long*)&b;
    unsigned long long C = *(unsigned long long*)&c;
    unsigned long long D;
    asm("fma.rn.f32x2 %0, %1, %2, %3;" : "=l"(D) : "l"(A), "l"(B), "l"(C));
    return *(float2*)&D;
}
__device__ __forceinline__ float2 fmul2(float2 a, float2 b) {
    unsigned long long A = *(unsigned long long*)&a;
    unsigned long long B = *(unsigned long long*)&b;
    unsigned long long D;
    asm("mul.rn.f32x2 %0, %1, %2;" : "=l"(D) : "l"(A), "l"(B));
    return *(float2*)&D;
}

// ---------------------------------------------------------------------------
// Kernel 1: fused data_bn (eval) + 1x1 qkv conv. 3 blocks per b (T split of 100).
// Scalar 4x4 register tile (proven fastest form).
// ---------------------------------------------------------------------------
__global__ void __launch_bounds__(256, 3) qkv_kernel(
    const float* __restrict__ x,
    const float* __restrict__ dg, const float* __restrict__ db,
    const float* __restrict__ dm, const float* __restrict__ dv,
    const float* __restrict__ W,  const float* __restrict__ Wb)
{
    int b = blockIdx.x;
    int T0 = blockIdx.y * 100;
    int n = b / Vv, v = b - n * Vv;
    extern __shared__ float sm[];
    float* xs = sm;             // 64*100
    float* Wt = xs + 6400;      // 12288  Wt[c*192+o] = W[o*64+c]
    float* sc = Wt + 12288;     // 64
    float* bi = sc + 64;        // 64
    int tid = threadIdx.x;

    if (tid < 64) {
        int idx = tid * Vv + v;
        float s = dg[idx] * rsqrtf(dv[idx] + 1e-5f);
        sc[tid] = s;
        bi[tid] = db[idx] - dm[idx] * s;
    }
    for (int i = tid; i < 192 * 64; i += 256) {
        int c = i / 192, o = i - c * 192;
        Wt[i] = W[o * 64 + c];
    }
    __syncthreads();

    const float* xb = x + ((size_t)n * Cc) * Tt * Vv + v;
    for (int i = tid; i < 64 * 100; i += 256) {
        int c = i / 100, tt = i - c * 100;
        xs[i] = xb[(size_t)(c * Tt + T0 + tt) * Vv] * sc[c] + bi[c];
    }
    __syncthreads();

    // 192x100 outputs in 4x4 tiles: 48*25 = 1200 tiles
    for (int tile = tid; tile < 1200; tile += 256) {
        int og = tile / 25, tg = tile - og * 25;
        int o0 = og * 4, t0 = tg * 4;
        float acc[4][4] = {};
        #pragma unroll 8
        for (int c = 0; c < 64; ++c) {
            float4 w4 = *(const float4*)(Wt + c * 192 + o0);
            float4 x4 = *(const float4*)(xs + c * 100 + t0);
            float wa[4] = {w4.x, w4.y, w4.z, w4.w};
            float xa[4] = {x4.x, x4.y, x4.z, x4.w};
            #pragma unroll
            for (int i = 0; i < 4; ++i)
                #pragma unroll
                for (int j = 0; j < 4; ++j)
                    acc[i][j] += wa[i] * xa[j];
        }
        float* outp = g_qkv + ((size_t)b * QKVO + o0) * Tt + T0 + t0;
        #pragma unroll
        for (int i = 0; i < 4; ++i) {
            float bias = Wb[o0 + i];
            float scale = (o0 + i < 64) ? 0.25f : 1.0f;  // q * DKH^-0.5
            float4 r;
            r.x = (acc[i][0] + bias) * scale;
            r.y = (acc[i][1] + bias) * scale;
            r.z = (acc[i][2] + bias) * scale;
            r.w = (acc[i][3] + bias) * scale;
            *(float4*)(outp + i * Tt) = r;
        }
    }
}

// ---------------------------------------------------------------------------
// Kernel 2: attention per (b,h). QK+softmax: warp owns 4 t-rows, packed f32x2
// logits across 3 s-passes. AV: lane = (d, s-half) -> all-distinct v loads
// (full crossbar efficiency), STG.128 output.
// ---------------------------------------------------------------------------
#define KST 300   // ks row stride
#define VST 316   // vs row stride (banks 28*d mod 32 -> conflict-free)
#define RST 600   // krs row stride
#define PST 132   // prob strip row stride

__global__ void __launch_bounds__(256, 2) attn_kernel(const float* __restrict__ key_rel)
{
    int bh = blockIdx.x;
    int b = bh >> 2, h = bh & 3;
    extern __shared__ float sm[];
    float* ks   = sm;                  // 16*300  [d][s]
    float* vs   = ks + 16 * KST;       // 16*316  [d][s]
    float* krs  = vs + 16 * VST;       // 16*600  [d][m]
    float* strp = krs + 16 * RST;      // 8 warps * 4*132

    const float* base = g_qkv + (size_t)b * QKVO * Tt;
    const float* qg = base + (h * 16) * Tt;
    const float* kg = base + (64 + h * 16) * Tt;
    const float* vg = base + (128 + h * 16) * Tt;

    int tid = threadIdx.x;
    for (int i = tid; i < 1200; i += 256)
        ((float4*)ks)[i] = ((const float4*)kg)[i];
    #pragma unroll
    for (int d = 0; d < 16; ++d)
        for (int t = tid; t < 300; t += 256)
            vs[d * VST + t] = vg[d * 300 + t];
    for (int i = tid; i < 599 * 16; i += 256) {
        int m = i >> 4, d = i & 15;
        krs[d * RST + m] = key_rel[i];
    }
    __syncthreads();

    int warp = tid >> 5, lane = tid & 31;
    float* stw = strp + warp * 4 * PST;
    int dl = lane & 15, sh = lane >> 4;     // AV lane mapping

    for (int g = warp; g < 75; g += 8) {
        int t0 = g * 4;
        float2 L[3][4][2];   // [p][i][jpair]
        bool v2 = (lane < 11);
        #pragma unroll
        for (int p = 0; p < 3; ++p) {
            float init = (p < 2 || v2) ? 0.f : -1e30f;
            #pragma unroll
            for (int i = 0; i < 4; ++i) {
                L[p][i][0] = make_float2(init, init);
                L[p][i][1] = make_float2(init, init);
            }
        }

        // ---- QK + rel (packed over s-pairs) ----
        #pragma unroll
        for (int d = 0; d < 16; ++d) {
            float4 q4 = __ldg((const float4*)(qg + d * 300 + t0));
            float2 qd[4] = { make_float2(q4.x, q4.x), make_float2(q4.y, q4.y),
                             make_float2(q4.z, q4.z), make_float2(q4.w, q4.w) };
            #pragma unroll
            for (int p = 0; p < 3; ++p) {
                if (p < 2 || v2) {
                    int s0 = p * 128 + lane * 4;
                    int m0 = s0 - t0 + 296;             // 16B-aligned base (kr[-3])
                    float4 k4 = *(const float4*)(ks + d * KST + s0);
                    float4 ra = *(const float4*)(krs + d * RST + m0);
                    float4 rb = *(const float4*)(krs + d * RST + m0 + 4);
                    float2 k01 = make_float2(k4.x, k4.y), k23 = make_float2(k4.z, k4.w);
                    float2 r01 = make_float2(ra.x, ra.y), r23 = make_float2(ra.z, ra.w);
                    float2 r45 = make_float2(rb.x, rb.y);
                    float2 r12 = make_float2(ra.y, ra.z);
                    float2 r34 = make_float2(ra.w, rb.x);
                    float2 r56 = make_float2(rb.y, rb.z);
                    L[p][0][0] = ffma2(qd[0], k01, L[p][0][0]); L[p][0][1] = ffma2(qd[0], k23, L[p][0][1]);
                    L[p][1][0] = ffma2(qd[1], k01, L[p][1][0]); L[p][1][1] = ffma2(qd[1], k23, L[p][1][1]);
                    L[p][2][0] = ffma2(qd[2], k01, L[p][2][0]); L[p][2][1] = ffma2(qd[2], k23, L[p][2][1]);
                    L[p][3][0] = ffma2(qd[3], k01, L[p][3][0]); L[p][3][1] = ffma2(qd[3], k23, L[p][3][1]);
                    L[p][0][0] = ffma2(qd[0], r34, L[p][0][0]); L[p][0][1] = ffma2(qd[0], r56, L[p][0][1]);
                    L[p][1][0] = ffma2(qd[1], r23, L[p][1][0]); L[p][1][1] = ffma2(qd[1], r45, L[p][1][1]);
                    L[p][2][0] = ffma2(qd[2], r12, L[p][2][0]); L[p][2][1] = ffma2(qd[2], r34, L[p][2][1]);
                    L[p][3][0] = ffma2(qd[3], r01, L[p][3][0]); L[p][3][1] = ffma2(qd[3], r23, L[p][3][1]);
                }
            }
        }

        // ---- softmax per row ----
        #pragma unroll
        for (int i = 0; i < 4; ++i) {
            float mx = -1e30f;
            #pragma unroll
            for (int p = 0; p < 3; ++p)
                #pragma unroll
                for (int jp = 0; jp < 2; ++jp)
                    mx = fmaxf(mx, fmaxf(L[p][i][jp].x, L[p][i][jp].y));
            #pragma unroll
            for (int o = 16; o > 0; o >>= 1)
                mx = fmaxf(mx, __shfl_xor_sync(0xffffffffu, mx, o));
            float s = 0.f;
            #pragma unroll
            for (int p = 0; p < 3; ++p)
                #pragma unroll
                for (int jp = 0; jp < 2; ++jp) {
                    float ex = __expf(L[p][i][jp].x - mx);
                    float ey = __expf(L[p][i][jp].y - mx);
                    L[p][i][jp] = make_float2(ex, ey);
                    s += ex + ey;
                }
            #pragma unroll
            for (int o = 16; o > 0; o >>= 1)
                s += __shfl_xor_sync(0xffffffffu, s, o);
            float inv = 1.f / s;
            float2 inv2 = make_float2(inv, inv);
            #pragma unroll
            for (int p = 0; p < 3; ++p)
                #pragma unroll
                for (int jp = 0; jp < 2; ++jp)
                    L[p][i][jp] = fmul2(L[p][i][jp], inv2);
        }

        // ---- AV: lane (dl, sh). v loads all-distinct; prob loads broadcast. ----
        float2 acc[4] = { {0.f,0.f}, {0.f,0.f}, {0.f,0.f}, {0.f,0.f} };
        #pragma unroll
        for (int p = 0; p < 3; ++p) {
            __syncwarp();
            // all lanes store their window slots (invalid lanes hold exact zeros)
            #pragma unroll
            for (int i = 0; i < 4; ++i) {
                float4 w4 = make_float4(L[p][i][0].x, L[p][i][0].y,
                                        L[p][i][1].x, L[p][i][1].y);
                *(float4*)(stw + i * PST + lane * 4) = w4;
            }
            __syncwarp();
            // p<2: 128 s split into two 64-halves; p==2: only 44 valid s, all in sh==0.
            const int iters = (p < 2) ? 16 : (sh == 0 ? 11 : 0);
            const float* vrow = vs + dl * VST + p * 128 + sh * 64;
            const float* pw = stw + sh * 64;
            #pragma unroll 4
            for (int s4 = 0; s4 < iters; ++s4) {
                float4 v4 = *(const float4*)(vrow + s4 * 4);
                float2 v01 = make_float2(v4.x, v4.y);
                float2 v23 = make_float2(v4.z, v4.w);
                #pragma unroll
                for (int i = 0; i < 4; ++i) {
                    float4 pr = *(const float4*)(pw + i * PST + s4 * 4);
                    acc[i] = ffma2(make_float2(pr.x, pr.y), v01, acc[i]);
                    acc[i] = ffma2(make_float2(pr.z, pr.w), v23, acc[i]);
                }
            }
        }
        // combine halves and write: lane (dl, 0) writes float4 over t0..t0+3
        float o[4];
        #pragma unroll
        for (int i = 0; i < 4; ++i) {
            float s = acc[i].x + acc[i].y;
            s += __shfl_xor_sync(0xffffffffu, s, 16);
            o[i] = s;
        }
        if (sh == 0) {
            float* ob = g_attn + ((size_t)b * 64 + h * 16 + dl) * Tt + t0;
            *(float4*)ob = make_float4(o[0], o[1], o[2], o[3]);
        }
    }
}

// ---------------------------------------------------------------------------
// Kernel 3: head-mix projection + skip + BN + ReLU. 2 blocks per b (T split).
// Scalar 4x4 register tile (proven form).
// ---------------------------------------------------------------------------
__global__ void __launch_bounds__(256, 4) proj_kernel(
    const float* __restrict__ Wa, const float* __restrict__ Ba,
    const float* __restrict__ bg, const float* __restrict__ bb,
    const float* __restrict__ bm, const float* __restrict__ bv,
    const float* __restrict__ x, float* __restrict__ out)
{
    int b = blockIdx.x;
    int half = blockIdx.y;
    int n = b / Vv, v = b - n * Vv;
    int T0 = half * 152;
    int TL = half ? 148 : 152;
    extern __shared__ float sm[];
    float* as = sm;            // 64*152
    float* Wt = as + 64 * 152; // 64*64   Wt[d*64+o] = Wa[o*64+d]
    float* s2 = Wt + 4096;     // 64
    float* b2 = s2 + 64;       // 64
    int tid = threadIdx.x;

    const float* ag = g_attn + (size_t)b * 64 * Tt;
    for (int i = tid; i < 64 * TL; i += 256) {
        int d = i / TL, tt = i - d * TL;
        as[d * 152 + tt] = ag[d * Tt + T0 + tt];
    }
    for (int i = tid; i < 4096; i += 256) {
        int d = i >> 6, o = i & 63;
        Wt[i] = Wa[o * 64 + d];
    }
    if (tid < 64) {
        float s = bg[tid] * rsqrtf(bv[tid] + 1e-5f);
        s2[tid] = s;
        b2[tid] = bb[tid] - bm[tid] * s;
    }
    __syncthreads();

    const float* xb = x + ((size_t)n * Cc) * Tt * Vv + v;
    float*       ob = out + ((size_t)n * Cc) * Tt * Vv + v;

    int tcols = TL >> 2;
    int ntile = 16 * tcols;
    for (int tile = tid; tile < ntile; tile += 256) {
        int og = tile / tcols, tg = tile - og * tcols;
        int o0 = og * 4, t0 = tg * 4;
        float acc[4][4] = {};
        #pragma unroll 8
        for (int d = 0; d < 64; ++d) {
            float4 w4 = *(const float4*)(Wt + d * 64 + o0);
            float4 a4 = *(const float4*)(as + d * 152 + t0);
            float wa[4] = {w4.x, w4.y, w4.z, w4.w};
            float aa[4] = {a4.x, a4.y, a4.z, a4.w};
            #pragma unroll
            for (int i = 0; i < 4; ++i)
                #pragma unroll
                for (int j = 0; j < 4; ++j)
                    acc[i][j] += wa[i] * aa[j];
        }
        #pragma unroll
        for (int i = 0; i < 4; ++i) {
            int o = o0 + i;
            float bias = Ba[o];
            #pragma unroll
            for (int j = 0; j < 4; ++j) {
                int t = T0 + t0 + j;
                size_t gi = (size_t)(o * Tt + t) * Vv;
                float r = acc[i][j] + bias + xb[gi];
                r = r * s2[o] + b2[o];
                ob[gi] = fmaxf(r, 0.f);
            }
        }
    }
}

// ---------------------------------------------------------------------------
extern "C" void kernel_launch(void* const* d_in, const int* in_sizes, int n_in,
                              void* d_out, int out_size)
{
    const float* x       = (const float*)d_in[0];
    const float* dbn_g   = (const float*)d_in[1];
    const float* dbn_b   = (const float*)d_in[2];
    const float* dbn_m   = (const float*)d_in[3];
    const float* dbn_v   = (const float*)d_in[4];
    const float* qkv_w   = (const float*)d_in[5];
    const float* qkv_b   = (const float*)d_in[6];
    const float* key_rel = (const float*)d_in[7];
    const float* attn_w  = (const float*)d_in[8];
    const float* attn_b  = (const float*)d_in[9];
    const float* bn_g    = (const float*)d_in[10];
    const float* bn_b    = (const float*)d_in[11];
    const float* bn_m    = (const float*)d_in[12];
    const float* bn_v    = (const float*)d_in[13];
    float* out = (float*)d_out;

    const int SM1 = (6400 + 12288 + 128) * 4;                           // 75,264
    const int SM2 = (16 * KST + 16 * VST + 16 * RST + 8 * 4 * PST) * 4; // 94,720
    const int SM3 = (64 * 152 + 4096 + 128) * 4;                        // 55,808

    cudaFuncSetAttribute(qkv_kernel,  cudaFuncAttributeMaxDynamicSharedMemorySize, SM1);
    cudaFuncSetAttribute(attn_kernel, cudaFuncAttributeMaxDynamicSharedMemorySize, SM2);
    cudaFuncSetAttribute(proj_kernel, cudaFuncAttributeMaxDynamicSharedMemorySize, SM3);

    qkv_kernel<<<dim3(Bb, 3), 256, SM1>>>(x, dbn_g, dbn_b, dbn_m, dbn_v, qkv_w, qkv_b);
    attn_kernel<<<Bb * NHh, 256, SM2>>>(key_rel);
    proj_kernel<<<dim3(Bb, 2), 256, SM3>>>(attn_w, attn_b, bn_g, bn_b, bn_m, bn_v, x, out);
}

// round 6
// speedup vs baseline: 1.8355x; 1.0437x over previous
#include <cuda_runtime.h>
#include <cuda_bf16.h>
#include <math.h>

#define Nn 16
#define Cc 64
#define Tt 300
#define Vv 25
#define NHh 4
#define Bb (Nn*Vv)          // 400
#define QKVO 192            // 2*DK+DV

__device__ float g_qkv[(size_t)Bb * QKVO * Tt];
__device__ float g_attn[(size_t)Bb * 64 * Tt];

// ---- packed fp32 helpers (FFMA2 / FMUL2 are PTX-only on sm_103a) ----
__device__ __forceinline__ float2 ffma2(float2 a, float2 b, float2 c) {
    unsigned long long A = *(unsigned long long*)&a;
    unsigned long long B = *(unsigned long long*)&b;
    unsigned long long C = *(unsigned long long*)&c;
    unsigned long long D;
    asm("fma.rn.f32x2 %0, %1, %2, %3;" : "=l"(D) : "l"(A), "l"(B), "l"(C));
    return *(float2*)&D;
}
__device__ __forceinline__ float2 fmul2(float2 a, float2 b) {
    unsigned long long A = *(unsigned long long*)&a;
    unsigned long long B = *(unsigned long long*)&b;
    unsigned long long D;
    asm("mul.rn.f32x2 %0, %1, %2;" : "=l"(D) : "l"(A), "l"(B));
    return *(float2*)&D;
}

// ---------------------------------------------------------------------------
// Kernel 1: fused data_bn (eval) + 1x1 qkv conv. 3 blocks per b (T split 100).
// Lane mapping: og fastest -> x4 broadcast, w4 contiguous (FMA-bound).
// ---------------------------------------------------------------------------
__global__ void __launch_bounds__(256, 3) qkv_kernel(
    const float* __restrict__ x,
    const float* __restrict__ dg, const float* __restrict__ db,
    const float* __restrict__ dm, const float* __restrict__ dv,
    const float* __restrict__ W,  const float* __restrict__ Wb)
{
    int b = blockIdx.x;
    int T0 = blockIdx.y * 100;
    int n = b / Vv, v = b - n * Vv;
    extern __shared__ float sm[];
    float* xs = sm;             // 64*100
    float* Wt = xs + 6400;      // 12288  Wt[c*192+o] = W[o*64+c]
    float* sc = Wt + 12288;     // 64
    float* bi = sc + 64;        // 64
    int tid = threadIdx.x;

    if (tid < 64) {
        int idx = tid * Vv + v;
        float s = dg[idx] * rsqrtf(dv[idx] + 1e-5f);
        sc[tid] = s;
        bi[tid] = db[idx] - dm[idx] * s;
    }
    for (int i = tid; i < 192 * 64; i += 256) {
        int c = i / 192, o = i - c * 192;
        Wt[i] = W[o * 64 + c];
    }
    __syncthreads();

    const float* xb = x + ((size_t)n * Cc) * Tt * Vv + v;
    for (int i = tid; i < 64 * 100; i += 256) {
        int c = i / 100, tt = i - c * 100;
        xs[i] = xb[(size_t)(c * Tt + T0 + tt) * Vv] * sc[c] + bi[c];
    }
    __syncthreads();

    // 1200 tiles: og = tile % 48 (fastest), tg = tile / 48
    for (int tile = tid; tile < 1200; tile += 256) {
        int tg = tile / 48, og = tile - tg * 48;
        int o0 = og * 4, t0 = tg * 4;
        float acc[4][4] = {};
        #pragma unroll 8
        for (int c = 0; c < 64; ++c) {
            float4 w4 = *(const float4*)(Wt + c * 192 + o0);
            float4 x4 = *(const float4*)(xs + c * 100 + t0);
            float wa[4] = {w4.x, w4.y, w4.z, w4.w};
            float xa[4] = {x4.x, x4.y, x4.z, x4.w};
            #pragma unroll
            for (int i = 0; i < 4; ++i)
                #pragma unroll
                for (int j = 0; j < 4; ++j)
                    acc[i][j] += wa[i] * xa[j];
        }
        float* outp = g_qkv + ((size_t)b * QKVO + o0) * Tt + T0 + t0;
        #pragma unroll
        for (int i = 0; i < 4; ++i) {
            float bias = Wb[o0 + i];
            float scale = (o0 + i < 64) ? 0.25f : 1.0f;  // q * DKH^-0.5
            float4 r;
            r.x = (acc[i][0] + bias) * scale;
            r.y = (acc[i][1] + bias) * scale;
            r.z = (acc[i][2] + bias) * scale;
            r.w = (acc[i][3] + bias) * scale;
            *(float4*)(outp + i * Tt) = r;
        }
    }
}

// ---------------------------------------------------------------------------
// Kernel 2: attention per (b,h). QK+softmax as R5 (register logits, f32x2).
// AV: register probs, s-major swizzled vt, butterfly select-merge reduction.
// ---------------------------------------------------------------------------
#define KST 300   // ks row stride
#define RST 600   // krs row stride

__global__ void __launch_bounds__(256, 2) attn_kernel(const float* __restrict__ key_rel)
{
    int bh = blockIdx.x;
    int b = bh >> 2, h = bh & 3;
    extern __shared__ float sm[];
    float* ks   = sm;                  // 16*300  [d][s]
    float* krs  = ks + 16 * KST;       // 16*600  [d][m]
    float* vt   = krs + 16 * RST;      // 384*16  [s][d] chunk-swizzled

    const float* base = g_qkv + (size_t)b * QKVO * Tt;
    const float* qg = base + (h * 16) * Tt;
    const float* kg = base + (64 + h * 16) * Tt;
    const float* vg = base + (128 + h * 16) * Tt;

    int tid = threadIdx.x;
    for (int i = tid; i < 1200; i += 256)
        ((float4*)ks)[i] = ((const float4*)kg)[i];
    for (int i = tid; i < 599 * 16; i += 256) {
        int m = i >> 4, d = i & 15;
        krs[d * RST + m] = key_rel[i];
    }
    // zero vt tail rows (s = 300..383): words 4800..6143 — disjoint from fill
    for (int i = tid + 4800; i < 6144; i += 256)
        vt[i] = 0.f;
    // vt fill: vt[s][d], 16B chunk c = d>>2 swizzled by (s>>2)&3
    for (int i = tid; i < 4800; i += 256) {
        int d = i / 300, s = i - d * 300;
        int c = d >> 2, w = (s >> 2) & 3;
        vt[s * 16 + ((c ^ w) << 2) + (d & 3)] = vg[i];
    }
    __syncthreads();

    int warp = tid >> 5, lane = tid & 31;
    int lw = lane & 3;                         // vt swizzle key for this lane
    // butterfly output indices for this lane
    int oi = (((lane >> 4) & 1) << 1) | ((lane >> 3) & 1);
    int odp = (((lane >> 2) & 1) << 1) | ((lane >> 1) & 1);
    int odb = lane & 1;

    for (int g = warp; g < 75; g += 8) {
        int t0 = g * 4;
        float2 L[3][4][2];   // [p][i][jpair]
        bool v2 = (lane < 11);
        #pragma unroll
        for (int p = 0; p < 3; ++p) {
            float init = (p < 2 || v2) ? 0.f : -1e30f;
            #pragma unroll
            for (int i = 0; i < 4; ++i) {
                L[p][i][0] = make_float2(init, init);
                L[p][i][1] = make_float2(init, init);
            }
        }

        // ---- QK + rel (packed over s-pairs) ----
        #pragma unroll
        for (int d = 0; d < 16; ++d) {
            float4 q4 = __ldg((const float4*)(qg + d * 300 + t0));
            float2 qd[4] = { make_float2(q4.x, q4.x), make_float2(q4.y, q4.y),
                             make_float2(q4.z, q4.z), make_float2(q4.w, q4.w) };
            #pragma unroll
            for (int p = 0; p < 3; ++p) {
                if (p < 2 || v2) {
                    int s0 = p * 128 + lane * 4;
                    int m0 = s0 - t0 + 296;
                    float4 k4 = *(const float4*)(ks + d * KST + s0);
                    float4 ra = *(const float4*)(krs + d * RST + m0);
                    float4 rb = *(const float4*)(krs + d * RST + m0 + 4);
                    float2 k01 = make_float2(k4.x, k4.y), k23 = make_float2(k4.z, k4.w);
                    float2 r01 = make_float2(ra.x, ra.y), r23 = make_float2(ra.z, ra.w);
                    float2 r45 = make_float2(rb.x, rb.y);
                    float2 r12 = make_float2(ra.y, ra.z);
                    float2 r34 = make_float2(ra.w, rb.x);
                    float2 r56 = make_float2(rb.y, rb.z);
                    L[p][0][0] = ffma2(qd[0], k01, L[p][0][0]); L[p][0][1] = ffma2(qd[0], k23, L[p][0][1]);
                    L[p][1][0] = ffma2(qd[1], k01, L[p][1][0]); L[p][1][1] = ffma2(qd[1], k23, L[p][1][1]);
                    L[p][2][0] = ffma2(qd[2], k01, L[p][2][0]); L[p][2][1] = ffma2(qd[2], k23, L[p][2][1]);
                    L[p][3][0] = ffma2(qd[3], k01, L[p][3][0]); L[p][3][1] = ffma2(qd[3], k23, L[p][3][1]);
                    L[p][0][0] = ffma2(qd[0], r34, L[p][0][0]); L[p][0][1] = ffma2(qd[0], r56, L[p][0][1]);
                    L[p][1][0] = ffma2(qd[1], r23, L[p][1][0]); L[p][1][1] = ffma2(qd[1], r45, L[p][1][1]);
                    L[p][2][0] = ffma2(qd[2], r12, L[p][2][0]); L[p][2][1] = ffma2(qd[2], r34, L[p][2][1]);
                    L[p][3][0] = ffma2(qd[3], r01, L[p][3][0]); L[p][3][1] = ffma2(qd[3], r23, L[p][3][1]);
                }
            }
        }

        // ---- softmax per row ----
        #pragma unroll
        for (int i = 0; i < 4; ++i) {
            float mx = -1e30f;
            #pragma unroll
            for (int p = 0; p < 3; ++p)
                #pragma unroll
                for (int jp = 0; jp < 2; ++jp)
                    mx = fmaxf(mx, fmaxf(L[p][i][jp].x, L[p][i][jp].y));
            #pragma unroll
            for (int o = 16; o > 0; o >>= 1)
                mx = fmaxf(mx, __shfl_xor_sync(0xffffffffu, mx, o));
            float s = 0.f;
            #pragma unroll
            for (int p = 0; p < 3; ++p)
                #pragma unroll
                for (int jp = 0; jp < 2; ++jp) {
                    float ex = __expf(L[p][i][jp].x - mx);
                    float ey = __expf(L[p][i][jp].y - mx);
                    L[p][i][jp] = make_float2(ex, ey);
                    s += ex + ey;
                }
            #pragma unroll
            for (int o = 16; o > 0; o >>= 1)
                s += __shfl_xor_sync(0xffffffffu, s, o);
            float inv = 1.f / s;
            float2 inv2 = make_float2(inv, inv);
            #pragma unroll
            for (int p = 0; p < 3; ++p)
                #pragma unroll
                for (int jp = 0; jp < 2; ++jp)
                    L[p][i][jp] = fmul2(L[p][i][jp], inv2);
        }

        // ---- AV: probs in registers, v from swizzled vt, 2 sweeps of 8 d ----
        #pragma unroll
        for (int sweep = 0; sweep < 2; ++sweep) {
            float2 r[16];   // r[i*4+dp]: partial out[t0+i][sweep*8+dp*2..+1]
            #pragma unroll
            for (int k = 0; k < 16; ++k) r[k] = make_float2(0.f, 0.f);

            #pragma unroll
            for (int p = 0; p < 3; ++p) {
                int sbase = p * 128 + lane * 4;
                #pragma unroll
                for (int j = 0; j < 4; ++j) {
                    const float* vp = vt + (sbase + j) * 16;
                    float4 va = *(const float4*)(vp + (((sweep * 2)     ^ lw) << 2));
                    float4 vb = *(const float4*)(vp + (((sweep * 2 + 1) ^ lw) << 2));
                    float2 v01 = make_float2(va.x, va.y);
                    float2 v23 = make_float2(va.z, va.w);
                    float2 v45 = make_float2(vb.x, vb.y);
                    float2 v67 = make_float2(vb.z, vb.w);
                    #pragma unroll
                    for (int i = 0; i < 4; ++i) {
                        float pij = (j & 1) ? L[p][i][j >> 1].y : L[p][i][j >> 1].x;
                        float2 pp = make_float2(pij, pij);
                        r[i * 4 + 0] = ffma2(pp, v01, r[i * 4 + 0]);
                        r[i * 4 + 1] = ffma2(pp, v23, r[i * 4 + 1]);
                        r[i * 4 + 2] = ffma2(pp, v45, r[i * 4 + 2]);
                        r[i * 4 + 3] = ffma2(pp, v67, r[i * 4 + 3]);
                    }
                }
            }

            // ---- select-merge butterfly: 32 scalars -> one per lane ----
            bool hi;
            hi = (lane & 16);
            #pragma unroll
            for (int k = 0; k < 8; ++k) {
                float2 keep = hi ? r[k + 8] : r[k];
                float2 send = hi ? r[k] : r[k + 8];
                keep.x += __shfl_xor_sync(0xffffffffu, send.x, 16);
                keep.y += __shfl_xor_sync(0xffffffffu, send.y, 16);
                r[k] = keep;
            }
            hi = (lane & 8);
            #pragma unroll
            for (int k = 0; k < 4; ++k) {
                float2 keep = hi ? r[k + 4] : r[k];
                float2 send = hi ? r[k] : r[k + 4];
                keep.x += __shfl_xor_sync(0xffffffffu, send.x, 8);
                keep.y += __shfl_xor_sync(0xffffffffu, send.y, 8);
                r[k] = keep;
            }
            hi = (lane & 4);
            #pragma unroll
            for (int k = 0; k < 2; ++k) {
                float2 keep = hi ? r[k + 2] : r[k];
                float2 send = hi ? r[k] : r[k + 2];
                keep.x += __shfl_xor_sync(0xffffffffu, send.x, 4);
                keep.y += __shfl_xor_sync(0xffffffffu, send.y, 4);
                r[k] = keep;
            }
            hi = (lane & 2);
            {
                float2 keep = hi ? r[1] : r[0];
                float2 send = hi ? r[0] : r[1];
                keep.x += __shfl_xor_sync(0xffffffffu, send.x, 2);
                keep.y += __shfl_xor_sync(0xffffffffu, send.y, 2);
                r[0] = keep;
            }
            {
                bool hb = (lane & 1);
                float keep = hb ? r[0].y : r[0].x;
                float send = hb ? r[0].x : r[0].y;
                float outv = keep + __shfl_xor_sync(0xffffffffu, send, 1);
                int d = sweep * 8 + odp * 2 + odb;
                g_attn[((size_t)b * 64 + h * 16 + d) * Tt + t0 + oi] = outv;
            }
        }
    }
}

// ---------------------------------------------------------------------------
// Kernel 3: head-mix projection + skip + BN + ReLU. 2 blocks per b (T split).
// Lane mapping: og fastest.
// ---------------------------------------------------------------------------
__global__ void __launch_bounds__(256, 4) proj_kernel(
    const float* __restrict__ Wa, const float* __restrict__ Ba,
    const float* __restrict__ bg, const float* __restrict__ bb,
    const float* __restrict__ bm, const float* __restrict__ bv,
    const float* __restrict__ x, float* __restrict__ out)
{
    int b = blockIdx.x;
    int half = blockIdx.y;
    int n = b / Vv, v = b - n * Vv;
    int T0 = half * 152;
    int TL = half ? 148 : 152;
    extern __shared__ float sm[];
    float* as = sm;            // 64*152
    float* Wt = as + 64 * 152; // 64*64   Wt[d*64+o] = Wa[o*64+d]
    float* s2 = Wt + 4096;     // 64
    float* b2 = s2 + 64;       // 64
    int tid = threadIdx.x;

    const float* ag = g_attn + (size_t)b * 64 * Tt;
    for (int i = tid; i < 64 * TL; i += 256) {
        int d = i / TL, tt = i - d * TL;
        as[d * 152 + tt] = ag[d * Tt + T0 + tt];
    }
    for (int i = tid; i < 4096; i += 256) {
        int d = i >> 6, o = i & 63;
        Wt[i] = Wa[o * 64 + d];
    }
    if (tid < 64) {
        float s = bg[tid] * rsqrtf(bv[tid] + 1e-5f);
        s2[tid] = s;
        b2[tid] = bb[tid] - bm[tid] * s;
    }
    __syncthreads();

    const float* xb = x + ((size_t)n * Cc) * Tt * Vv + v;
    float*       ob = out + ((size_t)n * Cc) * Tt * Vv + v;

    int tcols = TL >> 2;
    int ntile = 16 * tcols;
    for (int tile = tid; tile < ntile; tile += 256) {
        int og = tile & 15, tg = tile >> 4;
        int o0 = og * 4, t0 = tg * 4;
        float acc[4][4] = {};
        #pragma unroll 8
        for (int d = 0; d < 64; ++d) {
            float4 w4 = *(const float4*)(Wt + d * 64 + o0);
            float4 a4 = *(const float4*)(as + d * 152 + t0);
            float wa[4] = {w4.x, w4.y, w4.z, w4.w};
            float aa[4] = {a4.x, a4.y, a4.z, a4.w};
            #pragma unroll
            for (int i = 0; i < 4; ++i)
                #pragma unroll
                for (int j = 0; j < 4; ++j)
                    acc[i][j] += wa[i] * aa[j];
        }
        #pragma unroll
        for (int i = 0; i < 4; ++i) {
            int o = o0 + i;
            float bias = Ba[o];
            #pragma unroll
            for (int j = 0; j < 4; ++j) {
                int t = T0 + t0 + j;
                size_t gi = (size_t)(o * Tt + t) * Vv;
                float r = acc[i][j] + bias + xb[gi];
                r = r * s2[o] + b2[o];
                ob[gi] = fmaxf(r, 0.f);
            }
        }
    }
}

// ---------------------------------------------------------------------------
extern "C" void kernel_launch(void* const* d_in, const int* in_sizes, int n_in,
                              void* d_out, int out_size)
{
    const float* x       = (const float*)d_in[0];
    const float* dbn_g   = (const float*)d_in[1];
    const float* dbn_b   = (const float*)d_in[2];
    const float* dbn_m   = (const float*)d_in[3];
    const float* dbn_v   = (const float*)d_in[4];
    const float* qkv_w   = (const float*)d_in[5];
    const float* qkv_b   = (const float*)d_in[6];
    const float* key_rel = (const float*)d_in[7];
    const float* attn_w  = (const float*)d_in[8];
    const float* attn_b  = (const float*)d_in[9];
    const float* bn_g    = (const float*)d_in[10];
    const float* bn_b    = (const float*)d_in[11];
    const float* bn_m    = (const float*)d_in[12];
    const float* bn_v    = (const float*)d_in[13];
    float* out = (float*)d_out;

    const int SM1 = (6400 + 12288 + 128) * 4;                 // 75,264
    const int SM2 = (16 * KST + 16 * RST + 384 * 16) * 4;     // 82,176
    const int SM3 = (64 * 152 + 4096 + 128) * 4;              // 55,808

    cudaFuncSetAttribute(qkv_kernel,  cudaFuncAttributeMaxDynamicSharedMemorySize, SM1);
    cudaFuncSetAttribute(attn_kernel, cudaFuncAttributeMaxDynamicSharedMemorySize, SM2);
    cudaFuncSetAttribute(proj_kernel, cudaFuncAttributeMaxDynamicSharedMemorySize, SM3);

    qkv_kernel<<<dim3(Bb, 3), 256, SM1>>>(x, dbn_g, dbn_b, dbn_m, dbn_v, qkv_w, qkv_b);
    attn_kernel<<<Bb * NHh, 256, SM2>>>(key_rel);
    proj_kernel<<<dim3(Bb, 2), 256, SM3>>>(attn_w, attn_b, bn_g, bn_b, bn_m, bn_v, x, out);
}